// round 1
// baseline (speedup 1.0000x reference)
#include <cuda_runtime.h>
#include <cuda_bf16.h>

#define O_CH  256
#define C_IN  128
#define KH_N  24
#define N_IN  24
#define N_OUT 24
#define KS    5
#define VOL   (KS*KS*KS)              // 125
#define WH_SIZE ((size_t)O_CH*N_IN*C_IN*N_OUT)   // 18,874,368

// scratch: nearest-neighbor indices on SO(3) grid
__device__ int g_nn[N_IN * N_OUT];

// ---------------------------------------------------------------------------
// Kernel A: nn[a,b] = argmax_k <out_H[b]^T @ in_H[a], grid_H[k]>_F  (first max)
// ---------------------------------------------------------------------------
__global__ void nn_kernel(const float* __restrict__ in_H,
                          const float* __restrict__ out_H,
                          const float* __restrict__ grid_H) {
    int t = threadIdx.x;
    if (t >= N_IN * N_OUT) return;
    int a = t / N_OUT, b = t % N_OUT;
    float A[9], B[9], P[9];
#pragma unroll
    for (int i = 0; i < 9; i++) { A[i] = in_H[a * 9 + i]; B[i] = out_H[b * 9 + i]; }
    // P[i][j] = sum_k out_H[b][k][i] * in_H[a][k][j]   (out_inv = out_H^T)
#pragma unroll
    for (int i = 0; i < 3; i++)
#pragma unroll
        for (int j = 0; j < 3; j++) {
            float s = 0.f;
#pragma unroll
            for (int k = 0; k < 3; k++) s += B[k * 3 + i] * A[k * 3 + j];
            P[i * 3 + j] = s;
        }
    float best = -1e30f; int bi = 0;
    for (int kh = 0; kh < KH_N; kh++) {
        float s = 0.f;
#pragma unroll
        for (int i = 0; i < 9; i++) s += P[i] * grid_H[kh * 9 + i];
        if (s > best) { best = s; bi = kh; }   // strict > keeps FIRST max (jnp.argmax)
    }
    g_nn[t] = bi;
}

// ---------------------------------------------------------------------------
// Kernel B: wH[o,a,c,b] = weight_H[o,c,nn[a,b]]
// float4 stores: each (o,a,c) row is 24 floats = 6 float4 (16B aligned).
// gridDim = (72, 256): per o, 72 blocks x 256 threads = 18432 float4.
// a = tid/768 -> each block lies entirely within one a (768/256 = 3).
// ---------------------------------------------------------------------------
__global__ void wh_kernel(const float* __restrict__ weight_H,
                          float* __restrict__ out) {
    __shared__ int snn[N_OUT];
    const int o = blockIdx.y;
    const int a = blockIdx.x / 3;
    if (threadIdx.x < N_OUT) snn[threadIdx.x] = g_nn[a * N_OUT + threadIdx.x];
    __syncthreads();

    const int tid = blockIdx.x * 256 + threadIdx.x;     // 0..18431 within o
    const int q   = tid % 6;                            // which float4 in the row
    const int c   = (tid / 6) % C_IN;

    const float* row = weight_H + ((size_t)o * C_IN + c) * KH_N;  // 96B, L1-resident
    const int b0 = q * 4;
    float4 v;
    v.x = __ldg(row + snn[b0 + 0]);
    v.y = __ldg(row + snn[b0 + 1]);
    v.z = __ldg(row + snn[b0 + 2]);
    v.w = __ldg(row + snn[b0 + 3]);

    float4* dst = reinterpret_cast<float4*>(
        out + (((size_t)o * N_IN + a) * C_IN + c) * N_OUT) + q;
    *dst = v;
}

// ---------------------------------------------------------------------------
// Kernel C: wRn[o,b,p] = trilinear(weight_Rn[o], out_H[b]^T @ grid_Rn[:,p])
// One block per (b,o): volume (125 f32) + rotation (9 f32) in shared.
// ---------------------------------------------------------------------------
__global__ void wrn_kernel(const float* __restrict__ out_H,
                           const float* __restrict__ grid_Rn,
                           const float* __restrict__ weight_Rn,
                           float* __restrict__ out) {
    __shared__ float vol[VOL];
    __shared__ float R[9];
    const int b = blockIdx.x, o = blockIdx.y;
    const int t = threadIdx.x;
    if (t < VOL) vol[t] = weight_Rn[(size_t)o * VOL + t];
    if (t < 9)   R[t]   = out_H[b * 9 + t];
    __syncthreads();
    if (t >= VOL) return;

    const float g0 = grid_Rn[t], g1 = grid_Rn[VOL + t], g2 = grid_Rn[2 * VOL + t];
    // coords[i] = sum_j out_H[b][j][i] * grid_Rn[j]   (out_inv = transpose)
    float cz = R[0] * g0 + R[3] * g1 + R[6] * g2;
    float cy = R[1] * g0 + R[4] * g1 + R[7] * g2;
    float cx = R[2] * g0 + R[5] * g1 + R[8] * g2;
    // align_corners=True mapping to [0, KS-1]
    cz = (cz + 1.f) * 0.5f * (KS - 1);
    cy = (cy + 1.f) * 0.5f * (KS - 1);
    cx = (cx + 1.f) * 0.5f * (KS - 1);

    const float z0f = floorf(cz), y0f = floorf(cy), x0f = floorf(cx);
    const int z0 = (int)z0f, y0 = (int)y0f, x0 = (int)x0f;
    const float fz = cz - z0f, fy = cy - y0f, fx = cx - x0f;

    float acc = 0.f;
#pragma unroll
    for (int dz = 0; dz < 2; dz++)
#pragma unroll
        for (int dy = 0; dy < 2; dy++)
#pragma unroll
            for (int dx = 0; dx < 2; dx++) {
                const int iz = z0 + dz, iy = y0 + dy, ix = x0 + dx;
                const bool valid = (iz >= 0) & (iz < KS) & (iy >= 0) & (iy < KS)
                                 & (ix >= 0) & (ix < KS);
                const int ci = min(max(iz, 0), KS - 1) * 25
                             + min(max(iy, 0), KS - 1) * 5
                             + min(max(ix, 0), KS - 1);
                const float w = (dz ? fz : 1.f - fz) * (dy ? fy : 1.f - fy)
                              * (dx ? fx : 1.f - fx);
                acc += (valid ? vol[ci] : 0.f) * w;
            }

    out[WH_SIZE + ((size_t)o * N_OUT + b) * VOL + t] = acc;
}

// ---------------------------------------------------------------------------
extern "C" void kernel_launch(void* const* d_in, const int* in_sizes, int n_in,
                              void* d_out, int out_size) {
    const float* in_H      = (const float*)d_in[0];  // [24,3,3]
    const float* out_H     = (const float*)d_in[1];  // [24,3,3]
    const float* grid_H    = (const float*)d_in[2];  // [24,3,3]
    const float* grid_Rn   = (const float*)d_in[3];  // [3,5,5,5]
    const float* weight_H  = (const float*)d_in[4];  // [256,128,24]
    const float* weight_Rn = (const float*)d_in[5];  // [256,1,5,5,5]
    float* out = (float*)d_out;

    nn_kernel<<<1, N_IN * N_OUT>>>(in_H, out_H, grid_H);

    dim3 gB(72, O_CH);
    wh_kernel<<<gB, 256>>>(weight_H, out);

    dim3 gC(N_OUT, O_CH);
    wrn_kernel<<<gC, 128>>>(out_H, grid_Rn, weight_Rn, out);
}